// round 9
// baseline (speedup 1.0000x reference)
#include <cuda_runtime.h>
#include <stdint.h>
#include <math.h>

#define SQ   4096
#define EMB  1152
#define NH   16
#define HD   72
#define HALF 36
#define NSEG 8
#define QKV3 (3*EMB)

#define BQ 64
#define BK 64

#define QSTR  76   // Q hi/lo smem stride (floats)
#define KRSTR 76   // raw K smem stride
#define VRSTR 88   // raw V smem stride (80 dims incl. pad)
#define PSTR  72   // P^T smem stride

static __device__ float g_qkv[(size_t)SQ * QKV3];   // (S, 3E) scratch
static __device__ float g_attn[(size_t)SQ * EMB];   // (S, E) attention output

// ---------------------------------------------------------------------------
// helpers
// ---------------------------------------------------------------------------
__device__ __forceinline__ unsigned f2tf32(float x) {
    unsigned r;
    asm("cvt.rna.tf32.f32 %0, %1;" : "=r"(r) : "f"(x));
    return r;
}

__device__ __forceinline__ void mma_tf32(float c[4],
                                         unsigned a0, unsigned a1, unsigned a2, unsigned a3,
                                         unsigned b0, unsigned b1) {
    asm("mma.sync.aligned.m16n8k8.row.col.f32.tf32.tf32.f32 "
        "{%0,%1,%2,%3}, {%4,%5,%6,%7}, {%8,%9}, {%0,%1,%2,%3};"
        : "+f"(c[0]), "+f"(c[1]), "+f"(c[2]), "+f"(c[3])
        : "r"(a0), "r"(a1), "r"(a2), "r"(a3), "r"(b0), "r"(b1));
}

__device__ __forceinline__ void cp16(uint32_t dst, const float* src) {
    asm volatile("cp.async.cg.shared.global [%0], [%1], 16;" :: "r"(dst), "l"(src));
}
__device__ __forceinline__ void cp16p(uint32_t dst, const float* src, int nbytes) {
    asm volatile("cp.async.cg.shared.global [%0], [%1], 16, %2;"
                 :: "r"(dst), "l"(src), "r"(nbytes));
}
#define CP_COMMIT() asm volatile("cp.async.commit_group;" ::: "memory")
#define CP_WAIT1()  asm volatile("cp.async.wait_group 1;" ::: "memory")

__device__ __forceinline__ uint32_t smem_u32(const void* p) {
    return (uint32_t)__cvta_generic_to_shared(p);
}

// ---------------------------------------------------------------------------
// TF32 GEMM: C[M,N] = A[M,K]*B[N,K]^T + bias. cp.async raw tiles, cvt at use.
// BM=BN=128, BK=16, 256 thr, warp tile 64x32. Smem [m][k] stride 20.
// ---------------------------------------------------------------------------
template<int NN, int KK>
__global__ __launch_bounds__(256)
void gemm_tf32(const float* __restrict__ A, const float* __restrict__ B,
               const float* __restrict__ bias, float* __restrict__ C)
{
    __shared__ float As[2][128 * 20];
    __shared__ float Bs[2][128 * 20];

    const int bm   = blockIdx.y * 128;
    const int bn   = blockIdx.x * 128;
    const int tid  = threadIdx.x;
    const int warp = tid >> 5;
    const int lane = tid & 31;
    const int wm   = warp >> 2;
    const int wn   = warp & 3;
    const int r    = lane >> 2;
    const int c    = lane & 3;
    const int srow = tid >> 1;           // 0..127
    const int scol = (tid & 1) * 8;      // 0 or 8

    float acc[4][4][4];
    #pragma unroll
    for (int mt = 0; mt < 4; mt++)
        #pragma unroll
        for (int nt = 0; nt < 4; nt++)
            #pragma unroll
            for (int i = 0; i < 4; i++) acc[mt][nt][i] = 0.0f;

    const float* Ab = A + (size_t)(bm + srow) * KK + scol;
    const float* Bb = B + (size_t)(bn + srow) * KK + scol;
    const uint32_t uA = smem_u32(&As[0][srow * 20 + scol]);
    const uint32_t uB = smem_u32(&Bs[0][srow * 20 + scol]);
    const uint32_t STAGE = 128 * 20 * 4;

    const int NKT = KK / 16;

    // prologue: issue tile 0
    {
        cp16(uA, Ab);  cp16(uA + 16, Ab + 4);
        cp16(uB, Bb);  cp16(uB + 16, Bb + 4);
        CP_COMMIT();
    }

    for (int kt = 0; kt < NKT; kt++) {
        const int cur = kt & 1;
        if (kt + 1 < NKT) {
            const int k0 = (kt + 1) * 16;
            const uint32_t off = (cur ^ 1) * STAGE;
            cp16(uA + off, Ab + k0);  cp16(uA + off + 16, Ab + k0 + 4);
            cp16(uB + off, Bb + k0);  cp16(uB + off + 16, Bb + k0 + 4);
        }
        CP_COMMIT();
        CP_WAIT1();
        __syncthreads();

        const float* Sa = As[cur];
        const float* Sb = Bs[cur];
        #pragma unroll
        for (int kc = 0; kc < 16; kc += 8) {
            unsigned af[4][4], bf[4][2];
            #pragma unroll
            for (int mt = 0; mt < 4; mt++) {
                const int base = (wm * 64 + mt * 16 + r) * 20 + kc + c;
                af[mt][0] = f2tf32(Sa[base]);
                af[mt][1] = f2tf32(Sa[base + 160]);
                af[mt][2] = f2tf32(Sa[base + 4]);
                af[mt][3] = f2tf32(Sa[base + 164]);
            }
            #pragma unroll
            for (int nt = 0; nt < 4; nt++) {
                const int base = (wn * 32 + nt * 8 + r) * 20 + kc + c;
                bf[nt][0] = f2tf32(Sb[base]);
                bf[nt][1] = f2tf32(Sb[base + 4]);
            }
            #pragma unroll
            for (int mt = 0; mt < 4; mt++)
                #pragma unroll
                for (int nt = 0; nt < 4; nt++)
                    mma_tf32(acc[mt][nt], af[mt][0], af[mt][1], af[mt][2], af[mt][3],
                             bf[nt][0], bf[nt][1]);
        }
        __syncthreads();
    }

    #pragma unroll
    for (int nt = 0; nt < 4; nt++) {
        const int col = bn + wn * 32 + nt * 8 + 2 * c;
        const float2 bb = *(const float2*)(bias + col);
        #pragma unroll
        for (int mt = 0; mt < 4; mt++) {
            const int row0 = bm + wm * 64 + mt * 16 + r;
            float2 o0 = make_float2(acc[mt][nt][0] + bb.x, acc[mt][nt][1] + bb.y);
            float2 o1 = make_float2(acc[mt][nt][2] + bb.x, acc[mt][nt][3] + bb.y);
            *(float2*)&C[(size_t)row0 * NN + col]       = o0;
            *(float2*)&C[(size_t)(row0 + 8) * NN + col] = o1;
        }
    }
}

// ---------------------------------------------------------------------------
// RoPE in-place on q,k halves of g_qkv.
// ---------------------------------------------------------------------------
__global__ __launch_bounds__(256)
void rope_kernel(const float* __restrict__ cosT, const float* __restrict__ sinT)
{
    int idx = blockIdx.x * blockDim.x + threadIdx.x;
    const int total = SQ * 2 * NH * HALF;
    if (idx >= total) return;
    int d  = idx % HALF;
    int h  = (idx / HALF) % NH;
    int qk = (idx / (HALF * NH)) & 1;
    int s  = idx / (HALF * NH * 2);

    float* base = g_qkv + (size_t)s * QKV3 + qk * EMB + h * HD;
    float x1 = base[d];
    float x2 = base[d + HALF];
    float c  = cosT[(size_t)s * HD + d];
    float sn = sinT[(size_t)s * HD + d];
    base[d]        = x1 * c - x2 * sn;
    base[d + HALF] = x2 * c + x1 * sn;
}

// ---------------------------------------------------------------------------
// Tensor-core block-diagonal varlen flash attention.
// cp.async double-buffered raw K/V; hi/lo split + cvt at fragment load.
// S^T = K·Q^T 3xTF32; O^T = V^T·P^T single tf32.
// ---------------------------------------------------------------------------
#define ATTN_SMEM_BYTES ((2*BQ*QSTR + 2*BK*KRSTR + 2*BK*VRSTR + BK*PSTR) * 4 + (64+64+16) * 4)

__global__ __launch_bounds__(256)
void attn_kernel(const float* __restrict__ qkv, const int* __restrict__ cu,
                 float* __restrict__ out)
{
    extern __shared__ float sm[];
    float* Qh = sm;                        // [64][QSTR] tf32-hi of Q
    float* Ql = Qh + BQ * QSTR;            // [64][QSTR] tf32-lo of Q
    float* Kr = Ql + BQ * QSTR;            // [2][64][KRSTR] raw K
    float* Vr = Kr + 2 * BK * KRSTR;       // [2][64][VRSTR] raw V (pads 72..79 = 0)
    float* Ps = Vr + 2 * BK * VRSTR;       // [64][PSTR] tf32 P^T
    int* segq = (int*)(Ps + BK * PSTR);
    int* segk = segq + 64;
    int* cus  = segk + 64;

    const int tid  = threadIdx.x;
    const int lane = tid & 31;
    const int warp = tid >> 5;
    const int r    = lane >> 2;
    const int cq   = lane & 3;
    const int nb   = warp * 8;
    const int h    = blockIdx.y;
    const int q0   = blockIdx.x * BQ;

    if (tid <= NSEG) cus[tid] = cu[tid];
    __syncthreads();

    if (tid < BQ) {
        int p = q0 + tid;
        int s = 0;
        #pragma unroll
        for (int i = 1; i <= NSEG; i++) s += (p >= cus[i]);
        segq[tid] = s;
    }
    // k range computed locally (cus is synced; no dependence on segq smem)
    int sfirst = 0, slast = 0;
    #pragma unroll
    for (int i = 1; i <= NSEG; i++) {
        sfirst += (q0 >= cus[i]);
        slast  += (q0 + BQ - 1 >= cus[i]);
    }
    const int k_lo = cus[sfirst];
    const int k_hi = cus[slast + 1];
    const int NT   = (k_hi - k_lo + BK - 1) / BK;

    // load Q tile, split hi/lo
    #pragma unroll
    for (int it = 0; it < (BQ * HD) / 256; it++) {
        int idx = tid + it * 256;
        int d = idx % HD, row = idx / HD;
        float x = qkv[(size_t)(q0 + row) * QKV3 + h * HD + d];
        unsigned hb = f2tf32(x);
        float lo = x - __uint_as_float(hb);
        Qh[row * QSTR + d] = __uint_as_float(hb);
        Ql[row * QSTR + d] = __uint_as_float(f2tf32(lo));
    }
    // zero V pads (dims 72..79) in both buffers
    #pragma unroll
    for (int i = tid; i < 2 * BK * 8; i += 256) {
        int buf = i >= BK * 8;
        int j = i - buf * BK * 8;
        Vr[buf * BK * VRSTR + (j >> 3) * VRSTR + HD + (j & 7)] = 0.0f;
    }

    // precompute per-thread cp.async chunk geometry (9 chunks/thread)
    int prow[9], psrcoff[9];
    uint32_t pdst[9];
    const uint32_t uK = smem_u32(Kr);
    const uint32_t uV = smem_u32(Vr);
    const uint32_t KBYTES = BK * KRSTR * 4;
    const uint32_t VBYTES = BK * VRSTR * 4;
    #pragma unroll
    for (int i = 0; i < 9; i++) {
        int cch = tid + i * 256;            // 0..2303
        int half = cch >= 1152;             // 0:K 1:V
        int cc = cch - half * 1152;
        int row = cc / 18;
        int d4 = (cc % 18) * 4;
        prow[i] = row;
        psrcoff[i] = (half ? 2 * EMB : EMB) + h * HD + d4;
        pdst[i] = half ? (uV + (uint32_t)(row * VRSTR + d4) * 4)
                       : (uK + (uint32_t)(row * KRSTR + d4) * 4);
    }

    // issue tile 0
    {
        #pragma unroll
        for (int i = 0; i < 9; i++) {
            int key = k_lo + prow[i];
            int ok = (key < k_hi) ? 16 : 0;
            int sk = key < k_hi ? key : (k_hi - 1);
            cp16p(pdst[i], qkv + (size_t)sk * QKV3 + psrcoff[i], ok);
        }
        CP_COMMIT();
    }
    __syncthreads();   // Qh/Ql, segq, V pads visible

    const int sq0 = segq[nb + 2 * cq];
    const int sq1 = segq[nb + 2 * cq + 1];

    float m[2]  = {-1e30f, -1e30f};
    float l[2]  = {0.0f, 0.0f};
    float oa[5][4];
    #pragma unroll
    for (int mt = 0; mt < 5; mt++)
        #pragma unroll
        for (int i = 0; i < 4; i++) oa[mt][i] = 0.0f;

    const float scale = 0.11785113019775793f;  // 1/sqrt(72)

    for (int t = 0; t < NT; t++) {
        const int cur = t & 1;
        // issue next tile into other buffer
        if (t + 1 < NT) {
            const int kk1 = k_lo + (t + 1) * BK;
            const uint32_t boff = (cur ^ 1) ? 1u : 0u;
            #pragma unroll
            for (int i = 0; i < 9; i++) {
                int key = kk1 + prow[i];
                int ok = (key < k_hi) ? 16 : 0;
                int sk = key < k_hi ? key : (k_hi - 1);
                uint32_t extra = (pdst[i] >= uV) ? VBYTES : KBYTES;
                cp16p(pdst[i] + boff * extra, qkv + (size_t)sk * QKV3 + psrcoff[i], ok);
            }
        }
        CP_COMMIT();
        CP_WAIT1();

        const int kk0 = k_lo + t * BK;
        if (tid < BK) {
            int key = kk0 + tid;
            int s = -1;
            if (key < k_hi) {
                s = 0;
                #pragma unroll
                for (int i = 1; i <= NSEG; i++) s += (key >= cus[i]);
            }
            segk[tid] = s;
        }
        __syncthreads();

        const float* Krb = Kr + cur * BK * KRSTR;
        const float* Vrb = Vr + cur * BK * VRSTR;

        // ---- S^T = K·Q^T, 3xTF32 (split K at load) ----
        float sf[4][4];
        #pragma unroll
        for (int mt = 0; mt < 4; mt++)
            #pragma unroll
            for (int i = 0; i < 4; i++) sf[mt][i] = 0.0f;

        #pragma unroll
        for (int k0 = 0; k0 < HD; k0 += 8) {
            unsigned bh0 = __float_as_uint(Qh[(nb + r) * QSTR + k0 + cq]);
            unsigned bh1 = __float_as_uint(Qh[(nb + r) * QSTR + k0 + cq + 4]);
            unsigned bl0 = __float_as_uint(Ql[(nb + r) * QSTR + k0 + cq]);
            unsigned bl1 = __float_as_uint(Ql[(nb + r) * QSTR + k0 + cq + 4]);
            #pragma unroll
            for (int mt = 0; mt < 4; mt++) {
                const int kb = mt * 16;
                float k0v = Krb[(kb + r) * KRSTR + k0 + cq];
                float k1v = Krb[(kb + r + 8) * KRSTR + k0 + cq];
                float k2v = Krb[(kb + r) * KRSTR + k0 + cq + 4];
                float k3v = Krb[(kb + r + 8) * KRSTR + k0 + cq + 4];
                unsigned ah0 = f2tf32(k0v), ah1 = f2tf32(k1v);
                unsigned ah2 = f2tf32(k2v), ah3 = f2tf32(k3v);
                unsigned al0 = f2tf32(k0v - __uint_as_float(ah0));
                unsigned al1 = f2tf32(k1v - __uint_as_float(ah1));
                unsigned al2 = f2tf32(k2v - __uint_as_float(ah2));
                unsigned al3 = f2tf32(k3v - __uint_as_float(ah3));
                mma_tf32(sf[mt], ah0, ah1, ah2, ah3, bh0, bh1);
                mma_tf32(sf[mt], ah0, ah1, ah2, ah3, bl0, bl1);
                mma_tf32(sf[mt], al0, al1, al2, al3, bh0, bh1);
            }
        }

        int skr[4][2];
        #pragma unroll
        for (int mt = 0; mt < 4; mt++) {
            skr[mt][0] = segk[mt * 16 + r];
            skr[mt][1] = segk[mt * 16 + r + 8];
        }

        // ---- online softmax per query column ----
        const int sqv[2] = {sq0, sq1};
        #pragma unroll
        for (int qq = 0; qq < 2; qq++) {
            float mx = -1e30f;
            #pragma unroll
            for (int mt = 0; mt < 4; mt++) {
                float v0 = (skr[mt][0] == sqv[qq]) ? sf[mt][qq] * scale     : -1e30f;
                float v1 = (skr[mt][1] == sqv[qq]) ? sf[mt][qq + 2] * scale : -1e30f;
                sf[mt][qq]     = v0;
                sf[mt][qq + 2] = v1;
                mx = fmaxf(mx, fmaxf(v0, v1));
            }
            mx = fmaxf(mx, __shfl_xor_sync(0xffffffffu, mx, 4));
            mx = fmaxf(mx, __shfl_xor_sync(0xffffffffu, mx, 8));
            mx = fmaxf(mx, __shfl_xor_sync(0xffffffffu, mx, 16));

            float mn  = fmaxf(m[qq], mx);
            float fac = __expf(m[qq] - mn);
            m[qq] = mn;

            float sum = 0.0f;
            #pragma unroll
            for (int mt = 0; mt < 4; mt++) {
                float p0 = (sf[mt][qq]     > -1e29f) ? __expf(sf[mt][qq]     - mn) : 0.0f;
                float p1 = (sf[mt][qq + 2] > -1e29f) ? __expf(sf[mt][qq + 2] - mn) : 0.0f;
                sf[mt][qq]     = p0;
                sf[mt][qq + 2] = p1;
                sum += p0 + p1;
            }
            sum += __shfl_xor_sync(0xffffffffu, sum, 4);
            sum += __shfl_xor_sync(0xffffffffu, sum, 8);
            sum += __shfl_xor_sync(0xffffffffu, sum, 16);
            l[qq] = l[qq] * fac + sum;

            #pragma unroll
            for (int mt = 0; mt < 5; mt++) {
                oa[mt][qq]     *= fac;
                oa[mt][qq + 2] *= fac;
            }
        }

        // ---- stage P^T (rna tf32) ----
        #pragma unroll
        for (int mt = 0; mt < 4; mt++) {
            #pragma unroll
            for (int half = 0; half < 2; half++) {
                const int krow = mt * 16 + r + half * 8;
                unsigned h0 = f2tf32(sf[mt][half * 2]);
                unsigned h1 = f2tf32(sf[mt][half * 2 + 1]);
                *(float2*)&Ps[krow * PSTR + nb + 2 * cq] =
                    make_float2(__uint_as_float(h0), __uint_as_float(h1));
            }
        }
        __syncthreads();

        // ---- O^T += V^T·P^T (cvt V at load) ----
        #pragma unroll
        for (int k0 = 0; k0 < BK; k0 += 8) {
            unsigned b0 = __float_as_uint(Ps[(k0 + cq) * PSTR + nb + r]);
            unsigned b1 = __float_as_uint(Ps[(k0 + cq + 4) * PSTR + nb + r]);
            #pragma unroll
            for (int mt = 0; mt < 5; mt++) {
                const int db = mt * 16;
                unsigned a0 = f2tf32(Vrb[(k0 + cq) * VRSTR + db + r]);
                unsigned a1 = f2tf32(Vrb[(k0 + cq) * VRSTR + db + r + 8]);
                unsigned a2 = f2tf32(Vrb[(k0 + cq + 4) * VRSTR + db + r]);
                unsigned a3 = f2tf32(Vrb[(k0 + cq + 4) * VRSTR + db + r + 8]);
                mma_tf32(oa[mt], a0, a1, a2, a3, b0, b1);
            }
        }
        __syncthreads();   // end-of-iter: frees cur buffer, segk, Ps
    }

    // ---- normalize + store ----
    const float inv0 = 1.0f / l[0];
    const float inv1 = 1.0f / l[1];
    const size_t qa = (size_t)(q0 + nb + 2 * cq);
    const size_t qb = qa + 1;
    #pragma unroll
    for (int mt = 0; mt < 5; mt++) {
        int d0 = mt * 16 + r;
        int d1 = d0 + 8;
        if (d0 < HD) {
            out[qa * EMB + h * HD + d0] = oa[mt][0] * inv0;
            out[qb * EMB + h * HD + d0] = oa[mt][1] * inv1;
        }
        if (d1 < HD) {
            out[qa * EMB + h * HD + d1] = oa[mt][2] * inv0;
            out[qb * EMB + h * HD + d1] = oa[mt][3] * inv1;
        }
    }
}

// ---------------------------------------------------------------------------
extern "C" void kernel_launch(void* const* d_in, const int* in_sizes, int n_in,
                              void* d_out, int out_size)
{
    const float* hidden = (const float*)d_in[0];
    const int*   cu     = (const int*)  d_in[1];
    const float* cosT   = (const float*)d_in[2];
    const float* sinT   = (const float*)d_in[3];
    const float* w_qkv  = (const float*)d_in[4];
    const float* b_qkv  = (const float*)d_in[5];
    const float* w_out  = (const float*)d_in[6];
    const float* b_out  = (const float*)d_in[7];
    float* out = (float*)d_out;

    void* p_qkv = nullptr;
    void* p_attn = nullptr;
    cudaGetSymbolAddress(&p_qkv, g_qkv);
    cudaGetSymbolAddress(&p_attn, g_attn);
    float* qkv  = (float*)p_qkv;
    float* attn = (float*)p_attn;

    // 1) QKV projection
    dim3 g1(QKV3 / 128, SQ / 128);
    gemm_tf32<QKV3, EMB><<<g1, 256>>>(hidden, w_qkv, b_qkv, qkv);

    // 2) RoPE in place
    const int total = SQ * 2 * NH * HALF;
    rope_kernel<<<(total + 255) / 256, 256>>>(cosT, sinT);

    // 3) varlen block-diagonal attention
    cudaFuncSetAttribute(attn_kernel, cudaFuncAttributeMaxDynamicSharedMemorySize,
                         ATTN_SMEM_BYTES);
    attn_kernel<<<dim3(SQ / BQ, NH), 256, ATTN_SMEM_BYTES>>>(qkv, cu, attn);

    // 4) output projection
    dim3 g2(EMB / 128, SQ / 128);
    gemm_tf32<EMB, EMB><<<g2, 256>>>(attn, w_out, b_out, out);
}

// round 11
// speedup vs baseline: 1.1135x; 1.1135x over previous
#include <cuda_runtime.h>
#include <stdint.h>
#include <math.h>

#define SQ   4096
#define EMB  1152
#define NH   16
#define HD   72
#define HALF 36
#define NSEG 8
#define QKV3 (3*EMB)

#define BQ 64
#define BK 64

#define QSTR 76   // raw Q smem stride (floats)
#define KSTR 76   // K hi/lo smem stride
#define VSTR 88   // V smem stride (80 dims incl. pad)
#define PSTR 72   // P^T smem stride

static __device__ float g_qkv[(size_t)SQ * QKV3];   // (S, 3E) scratch
static __device__ float g_attn[(size_t)SQ * EMB];   // (S, E) attention output

// ---------------------------------------------------------------------------
// TF32 helpers
// ---------------------------------------------------------------------------
__device__ __forceinline__ unsigned f2tf32(float x) {
    unsigned r;
    asm("cvt.rna.tf32.f32 %0, %1;" : "=r"(r) : "f"(x));
    return r;
}

__device__ __forceinline__ void mma_tf32(float c[4],
                                         unsigned a0, unsigned a1, unsigned a2, unsigned a3,
                                         unsigned b0, unsigned b1) {
    asm("mma.sync.aligned.m16n8k8.row.col.f32.tf32.tf32.f32 "
        "{%0,%1,%2,%3}, {%4,%5,%6,%7}, {%8,%9}, {%0,%1,%2,%3};"
        : "+f"(c[0]), "+f"(c[1]), "+f"(c[2]), "+f"(c[3])
        : "r"(a0), "r"(a1), "r"(a2), "r"(a3), "r"(b0), "r"(b1));
}

// ---------------------------------------------------------------------------
// TF32 tensor-core GEMM, software-pipelined + double-buffered smem (R6 best).
// C[M,N] = A[M,K] * B[N,K]^T + bias[N]
// ---------------------------------------------------------------------------
template<int NN, int KK>
__global__ __launch_bounds__(256)
void gemm_tf32(const float* __restrict__ A, const float* __restrict__ B,
               const float* __restrict__ bias, float* __restrict__ C)
{
    __shared__ unsigned As[2][16][136];
    __shared__ unsigned Bs[2][16][136];

    const int bm   = blockIdx.y * 128;
    const int bn   = blockIdx.x * 128;
    const int tid  = threadIdx.x;
    const int warp = tid >> 5;
    const int lane = tid & 31;
    const int wm   = warp >> 2;
    const int wn   = warp & 3;
    const int r    = lane >> 2;
    const int c    = lane & 3;
    const int lrow = tid >> 2;
    const int lcol = (tid & 3) << 2;

    float acc[4][4][4];
    #pragma unroll
    for (int mt = 0; mt < 4; mt++)
        #pragma unroll
        for (int nt = 0; nt < 4; nt++)
            #pragma unroll
            for (int i = 0; i < 4; i++) acc[mt][nt][i] = 0.0f;

    const float* Aptr = A + (size_t)(bm + lrow) * KK + lcol;
    const float* Bptr = B + (size_t)(bn + lrow) * KK + lcol;

    float4 ga0, ga1, gb0, gb1;
    ga0 = *(const float4*)(Aptr);
    ga1 = *(const float4*)(Aptr + (size_t)64 * KK);
    gb0 = *(const float4*)(Bptr);
    gb1 = *(const float4*)(Bptr + (size_t)64 * KK);

    {
        float av0[4] = {ga0.x, ga0.y, ga0.z, ga0.w};
        float av1[4] = {ga1.x, ga1.y, ga1.z, ga1.w};
        float bv0[4] = {gb0.x, gb0.y, gb0.z, gb0.w};
        float bv1[4] = {gb1.x, gb1.y, gb1.z, gb1.w};
        #pragma unroll
        for (int j = 0; j < 4; j++) {
            int k = lcol + j;
            int s = ((k >> 2) & 3) << 3;
            As[0][k][lrow ^ s]        = f2tf32(av0[j]);
            As[0][k][(lrow + 64) ^ s] = f2tf32(av1[j]);
            Bs[0][k][lrow ^ s]        = f2tf32(bv0[j]);
            Bs[0][k][(lrow + 64) ^ s] = f2tf32(bv1[j]);
        }
    }
    __syncthreads();

    const int NKT = KK / 16;
    for (int kt = 0; kt < NKT; kt++) {
        const int cur = kt & 1;
        if (kt + 1 < NKT) {
            const int k0 = (kt + 1) * 16;
            ga0 = *(const float4*)(Aptr + k0);
            ga1 = *(const float4*)(Aptr + (size_t)64 * KK + k0);
            gb0 = *(const float4*)(Bptr + k0);
            gb1 = *(const float4*)(Bptr + (size_t)64 * KK + k0);
        }

        #pragma unroll
        for (int kc = 0; kc < 16; kc += 8) {
            const int s0 = ((kc >> 2) & 3) << 3;
            const int s1 = (((kc >> 2) + 1) & 3) << 3;

            unsigned af[4][4], bf[4][2];
            #pragma unroll
            for (int mt = 0; mt < 4; mt++) {
                const int mb = wm * 64 + mt * 16;
                af[mt][0] = As[cur][kc + c][(mb + r) ^ s0];
                af[mt][1] = As[cur][kc + c][(mb + r + 8) ^ s0];
                af[mt][2] = As[cur][kc + c + 4][(mb + r) ^ s1];
                af[mt][3] = As[cur][kc + c + 4][(mb + r + 8) ^ s1];
            }
            #pragma unroll
            for (int nt = 0; nt < 4; nt++) {
                const int nb = wn * 32 + nt * 8;
                bf[nt][0] = Bs[cur][kc + c][(nb + r) ^ s0];
                bf[nt][1] = Bs[cur][kc + c + 4][(nb + r) ^ s1];
            }
            #pragma unroll
            for (int mt = 0; mt < 4; mt++)
                #pragma unroll
                for (int nt = 0; nt < 4; nt++)
                    mma_tf32(acc[mt][nt], af[mt][0], af[mt][1], af[mt][2], af[mt][3],
                             bf[nt][0], bf[nt][1]);
        }

        if (kt + 1 < NKT) {
            const int nxt = cur ^ 1;
            float av0[4] = {ga0.x, ga0.y, ga0.z, ga0.w};
            float av1[4] = {ga1.x, ga1.y, ga1.z, ga1.w};
            float bv0[4] = {gb0.x, gb0.y, gb0.z, gb0.w};
            float bv1[4] = {gb1.x, gb1.y, gb1.z, gb1.w};
            #pragma unroll
            for (int j = 0; j < 4; j++) {
                int k = lcol + j;
                int s = ((k >> 2) & 3) << 3;
                As[nxt][k][lrow ^ s]        = f2tf32(av0[j]);
                As[nxt][k][(lrow + 64) ^ s] = f2tf32(av1[j]);
                Bs[nxt][k][lrow ^ s]        = f2tf32(bv0[j]);
                Bs[nxt][k][(lrow + 64) ^ s] = f2tf32(bv1[j]);
            }
            __syncthreads();
        }
    }

    #pragma unroll
    for (int nt = 0; nt < 4; nt++) {
        const int col = bn + wn * 32 + nt * 8 + 2 * c;
        const float2 bb = *(const float2*)(bias + col);
        #pragma unroll
        for (int mt = 0; mt < 4; mt++) {
            const int row0 = bm + wm * 64 + mt * 16 + r;
            float2 o0 = make_float2(acc[mt][nt][0] + bb.x, acc[mt][nt][1] + bb.y);
            float2 o1 = make_float2(acc[mt][nt][2] + bb.x, acc[mt][nt][3] + bb.y);
            *(float2*)&C[(size_t)row0 * NN + col]       = o0;
            *(float2*)&C[(size_t)(row0 + 8) * NN + col] = o1;
        }
    }
}

// ---------------------------------------------------------------------------
// RoPE in-place on q,k halves of g_qkv.
// ---------------------------------------------------------------------------
__global__ __launch_bounds__(256)
void rope_kernel(const float* __restrict__ cosT, const float* __restrict__ sinT)
{
    int idx = blockIdx.x * blockDim.x + threadIdx.x;
    const int total = SQ * 2 * NH * HALF;
    if (idx >= total) return;
    int d  = idx % HALF;
    int h  = (idx / HALF) % NH;
    int qk = (idx / (HALF * NH)) & 1;
    int s  = idx / (HALF * NH * 2);

    float* base = g_qkv + (size_t)s * QKV3 + qk * EMB + h * HD;
    float x1 = base[d];
    float x2 = base[d + HALF];
    float c  = cosT[(size_t)s * HD + d];
    float sn = sinT[(size_t)s * HD + d];
    base[d]        = x1 * c - x2 * sn;
    base[d + HALF] = x2 * c + x1 * sn;
}

// ---------------------------------------------------------------------------
// Tensor-core block-diagonal varlen flash attention.
// Q raw in smem (split hi/lo at fragment load); K staged hi/lo; V tf32.
// S^T = K·Q^T 3xTF32; O^T = V^T·P^T single tf32.
// Smem ~100 KB => 2 CTAs/SM.
// ---------------------------------------------------------------------------
#define ATTN_SMEM_BYTES ((BQ*QSTR + 2*BK*KSTR + BK*VSTR + BK*PSTR) * 4 + (64 + 64 + 16) * 4)

__global__ __launch_bounds__(256, 2)
void attn_kernel(const float* __restrict__ qkv, const int* __restrict__ cu,
                 float* __restrict__ out)
{
    extern __shared__ float sm[];
    float* Qs = sm;                       // [64][QSTR] raw Q (query, dim)
    float* Kh = Qs + BQ * QSTR;           // [64][KSTR] tf32-hi of K (key, dim)
    float* Kl = Kh + BK * KSTR;           // [64][KSTR] tf32-lo of K
    float* Vs = Kl + BK * KSTR;           // [64][VSTR] tf32 V (key, dim), 72..79 zero
    float* Ps = Vs + BK * VSTR;           // [64][PSTR] tf32 P^T (key, query)
    int* segq = (int*)(Ps + BK * PSTR);
    int* segk = segq + 64;
    int* cus  = segk + 64;

    const int tid  = threadIdx.x;
    const int lane = tid & 31;
    const int warp = tid >> 5;
    const int r    = lane >> 2;
    const int cq   = lane & 3;
    const int nb   = warp * 8;
    const int h    = blockIdx.y;
    const int q0   = blockIdx.x * BQ;

    if (tid <= NSEG) cus[tid] = cu[tid];
    __syncthreads();

    if (tid < BQ) {
        int p = q0 + tid;
        int s = 0;
        #pragma unroll
        for (int i = 1; i <= NSEG; i++) s += (p >= cus[i]);
        segq[tid] = s;
    }
    // load Q tile raw
    #pragma unroll
    for (int it = 0; it < (BQ * HD) / 256; it++) {
        int idx = tid + it * 256;
        int d = idx % HD, row = idx / HD;
        Qs[row * QSTR + d] = qkv[(size_t)(q0 + row) * QKV3 + h * HD + d];
    }
    // zero V padding dims 72..79
    #pragma unroll
    for (int i = tid; i < BK * 8; i += 256)
        Vs[(i >> 3) * VSTR + HD + (i & 7)] = 0.0f;
    __syncthreads();

    const int sq0 = segq[nb + 2 * cq];
    const int sq1 = segq[nb + 2 * cq + 1];
    const int k_lo = cus[segq[0]];
    const int k_hi = cus[segq[BQ - 1] + 1];

    float m[2]  = {-1e30f, -1e30f};
    float l[2]  = {0.0f, 0.0f};
    float oa[5][4];
    #pragma unroll
    for (int mt = 0; mt < 5; mt++)
        #pragma unroll
        for (int i = 0; i < 4; i++) oa[mt][i] = 0.0f;

    const float scale = 0.11785113019775793f;  // 1/sqrt(72)

    for (int kk0 = k_lo; kk0 < k_hi; kk0 += BK) {
        // ---- load K (split hi/lo at staging) and V (tf32) tiles ----
        #pragma unroll
        for (int it = 0; it < (BK * HD) / 256; it++) {
            int idx = tid + it * 256;
            int d = idx % HD, ky = idx / HD;
            int key = kk0 + ky;
            float kv = 0.0f, vv = 0.0f;
            if (key < k_hi) {
                const float* row = qkv + (size_t)key * QKV3 + h * HD + d;
                kv = row[EMB];
                vv = row[2 * EMB];
            }
            unsigned hb = f2tf32(kv);
            float lo = kv - __uint_as_float(hb);
            Kh[ky * KSTR + d] = __uint_as_float(hb);
            Kl[ky * KSTR + d] = __uint_as_float(f2tf32(lo));
            Vs[ky * VSTR + d] = __uint_as_float(f2tf32(vv));
        }
        if (tid < BK) {
            int key = kk0 + tid;
            int s = -1;
            if (key < k_hi) {
                s = 0;
                #pragma unroll
                for (int i = 1; i <= NSEG; i++) s += (key >= cus[i]);
            }
            segk[tid] = s;
        }
        __syncthreads();

        // ---- S^T = K·Q^T, 3xTF32: Kh*Qh + Kh*Ql + Kl*Qh (Q split at load) ----
        float sf[4][4];
        #pragma unroll
        for (int mt = 0; mt < 4; mt++)
            #pragma unroll
            for (int i = 0; i < 4; i++) sf[mt][i] = 0.0f;

        #pragma unroll
        for (int k0 = 0; k0 < HD; k0 += 8) {
            float q0v = Qs[(nb + r) * QSTR + k0 + cq];
            float q1v = Qs[(nb + r) * QSTR + k0 + cq + 4];
            unsigned bh0 = f2tf32(q0v);
            unsigned bh1 = f2tf32(q1v);
            unsigned bl0 = f2tf32(q0v - __uint_as_float(bh0));
            unsigned bl1 = f2tf32(q1v - __uint_as_float(bh1));
            #pragma unroll
            for (int mt = 0; mt < 4; mt++) {
                const int kb = mt * 16;
                unsigned ah0 = __float_as_uint(Kh[(kb + r) * KSTR + k0 + cq]);
                unsigned ah1 = __float_as_uint(Kh[(kb + r + 8) * KSTR + k0 + cq]);
                unsigned ah2 = __float_as_uint(Kh[(kb + r) * KSTR + k0 + cq + 4]);
                unsigned ah3 = __float_as_uint(Kh[(kb + r + 8) * KSTR + k0 + cq + 4]);
                unsigned al0 = __float_as_uint(Kl[(kb + r) * KSTR + k0 + cq]);
                unsigned al1 = __float_as_uint(Kl[(kb + r + 8) * KSTR + k0 + cq]);
                unsigned al2 = __float_as_uint(Kl[(kb + r) * KSTR + k0 + cq + 4]);
                unsigned al3 = __float_as_uint(Kl[(kb + r + 8) * KSTR + k0 + cq + 4]);
                mma_tf32(sf[mt], ah0, ah1, ah2, ah3, bh0, bh1);
                mma_tf32(sf[mt], ah0, ah1, ah2, ah3, bl0, bl1);
                mma_tf32(sf[mt], al0, al1, al2, al3, bh0, bh1);
            }
        }

        int skr[4][2];
        #pragma unroll
        for (int mt = 0; mt < 4; mt++) {
            skr[mt][0] = segk[mt * 16 + r];
            skr[mt][1] = segk[mt * 16 + r + 8];
        }

        // ---- online softmax per query column ----
        const int sqv[2] = {sq0, sq1};
        #pragma unroll
        for (int qq = 0; qq < 2; qq++) {
            float mx = -1e30f;
            #pragma unroll
            for (int mt = 0; mt < 4; mt++) {
                float v0 = (skr[mt][0] == sqv[qq]) ? sf[mt][qq] * scale     : -1e30f;
                float v1 = (skr[mt][1] == sqv[qq]) ? sf[mt][qq + 2] * scale : -1e30f;
                sf[mt][qq]     = v0;
                sf[mt][qq + 2] = v1;
                mx = fmaxf(mx, fmaxf(v0, v1));
            }
            mx = fmaxf(mx, __shfl_xor_sync(0xffffffffu, mx, 4));
            mx = fmaxf(mx, __shfl_xor_sync(0xffffffffu, mx, 8));
            mx = fmaxf(mx, __shfl_xor_sync(0xffffffffu, mx, 16));

            float mn  = fmaxf(m[qq], mx);
            float fac = __expf(m[qq] - mn);
            m[qq] = mn;

            float sum = 0.0f;
            #pragma unroll
            for (int mt = 0; mt < 4; mt++) {
                float p0 = (sf[mt][qq]     > -1e29f) ? __expf(sf[mt][qq]     - mn) : 0.0f;
                float p1 = (sf[mt][qq + 2] > -1e29f) ? __expf(sf[mt][qq + 2] - mn) : 0.0f;
                sf[mt][qq]     = p0;
                sf[mt][qq + 2] = p1;
                sum += p0 + p1;
            }
            sum += __shfl_xor_sync(0xffffffffu, sum, 4);
            sum += __shfl_xor_sync(0xffffffffu, sum, 8);
            sum += __shfl_xor_sync(0xffffffffu, sum, 16);
            l[qq] = l[qq] * fac + sum;

            #pragma unroll
            for (int mt = 0; mt < 5; mt++) {
                oa[mt][qq]     *= fac;
                oa[mt][qq + 2] *= fac;
            }
        }

        // ---- stage P^T (rna tf32) ----
        #pragma unroll
        for (int mt = 0; mt < 4; mt++) {
            #pragma unroll
            for (int half = 0; half < 2; half++) {
                const int krow = mt * 16 + r + half * 8;
                unsigned h0 = f2tf32(sf[mt][half * 2]);
                unsigned h1 = f2tf32(sf[mt][half * 2 + 1]);
                *(float2*)&Ps[krow * PSTR + nb + 2 * cq] =
                    make_float2(__uint_as_float(h0), __uint_as_float(h1));
            }
        }
        __syncthreads();

        // ---- O^T += V^T·P^T ----
        #pragma unroll
        for (int k0 = 0; k0 < BK; k0 += 8) {
            unsigned b0 = __float_as_uint(Ps[(k0 + cq) * PSTR + nb + r]);
            unsigned b1 = __float_as_uint(Ps[(k0 + cq + 4) * PSTR + nb + r]);
            #pragma unroll
            for (int mt = 0; mt < 5; mt++) {
                const int db = mt * 16;
                unsigned a0 = __float_as_uint(Vs[(k0 + cq) * VSTR + db + r]);
                unsigned a1 = __float_as_uint(Vs[(k0 + cq) * VSTR + db + r + 8]);
                unsigned a2 = __float_as_uint(Vs[(k0 + cq + 4) * VSTR + db + r]);
                unsigned a3 = __float_as_uint(Vs[(k0 + cq + 4) * VSTR + db + r + 8]);
                mma_tf32(oa[mt], a0, a1, a2, a3, b0, b1);
            }
        }
        __syncthreads();
    }

    // ---- normalize + store ----
    const float inv0 = 1.0f / l[0];
    const float inv1 = 1.0f / l[1];
    const size_t qa = (size_t)(q0 + nb + 2 * cq);
    const size_t qb = qa + 1;
    #pragma unroll
    for (int mt = 0; mt < 5; mt++) {
        int d0 = mt * 16 + r;
        int d1 = d0 + 8;
        if (d0 < HD) {
            out[qa * EMB + h * HD + d0] = oa[mt][0] * inv0;
            out[qb * EMB + h * HD + d0] = oa[mt][1] * inv1;
        }
        if (d1 < HD) {
            out[qa * EMB + h * HD + d1] = oa[mt][2] * inv0;
            out[qb * EMB + h * HD + d1] = oa[mt][3] * inv1;
        }
    }
}

// ---------------------------------------------------------------------------
extern "C" void kernel_launch(void* const* d_in, const int* in_sizes, int n_in,
                              void* d_out, int out_size)
{
    const float* hidden = (const float*)d_in[0];
    const int*   cu     = (const int*)  d_in[1];
    const float* cosT   = (const float*)d_in[2];
    const float* sinT   = (const float*)d_in[3];
    const float* w_qkv  = (const float*)d_in[4];
    const float* b_qkv  = (const float*)d_in[5];
    const float* w_out  = (const float*)d_in[6];
    const float* b_out  = (const float*)d_in[7];
    float* out = (float*)d_out;

    void* p_qkv = nullptr;
    void* p_attn = nullptr;
    cudaGetSymbolAddress(&p_qkv, g_qkv);
    cudaGetSymbolAddress(&p_attn, g_attn);
    float* qkv  = (float*)p_qkv;
    float* attn = (float*)p_attn;

    // 1) QKV projection
    dim3 g1(QKV3 / 128, SQ / 128);
    gemm_tf32<QKV3, EMB><<<g1, 256>>>(hidden, w_qkv, b_qkv, qkv);

    // 2) RoPE in place
    const int total = SQ * 2 * NH * HALF;
    rope_kernel<<<(total + 255) / 256, 256>>>(cosT, sinT);

    // 3) varlen block-diagonal attention (2 CTAs/SM)
    cudaFuncSetAttribute(attn_kernel, cudaFuncAttributeMaxDynamicSharedMemorySize,
                         ATTN_SMEM_BYTES);
    attn_kernel<<<dim3(SQ / BQ, NH), 256, ATTN_SMEM_BYTES>>>(qkv, cu, attn);

    // 4) output projection
    dim3 g2(EMB / 128, SQ / 128);
    gemm_tf32<EMB, EMB><<<g2, 256>>>(attn, w_out, b_out, out);
}

// round 13
// speedup vs baseline: 1.1380x; 1.0220x over previous
#include <cuda_runtime.h>
#include <stdint.h>
#include <math.h>

#define SQ   4096
#define EMB  1152
#define NH   16
#define HD   72
#define HALF 36
#define NSEG 8
#define QKV3 (3*EMB)

#define BQ 64
#define BK 64

#define QSTR  76   // raw Q smem stride (floats), 304B rows
#define KSTR  76   // K hi/lo smem stride, 304B rows
#define VTSTR 68   // V^T smem stride (keys + pad), 272B rows
#define PQSTR 68   // P[query][key] stride, 272B rows

static __device__ float g_qkv[(size_t)SQ * QKV3];   // (S, 3E) scratch
static __device__ float g_attn[(size_t)SQ * EMB];   // (S, E) attention output

// ---------------------------------------------------------------------------
// TF32 / ldmatrix helpers
// ---------------------------------------------------------------------------
__device__ __forceinline__ unsigned f2tf32(float x) {
    unsigned r;
    asm("cvt.rna.tf32.f32 %0, %1;" : "=r"(r) : "f"(x));
    return r;
}

__device__ __forceinline__ void mma_tf32(float c[4],
                                         unsigned a0, unsigned a1, unsigned a2, unsigned a3,
                                         unsigned b0, unsigned b1) {
    asm("mma.sync.aligned.m16n8k8.row.col.f32.tf32.tf32.f32 "
        "{%0,%1,%2,%3}, {%4,%5,%6,%7}, {%8,%9}, {%0,%1,%2,%3};"
        : "+f"(c[0]), "+f"(c[1]), "+f"(c[2]), "+f"(c[3])
        : "r"(a0), "r"(a1), "r"(a2), "r"(a3), "r"(b0), "r"(b1));
}

__device__ __forceinline__ void ldsm_x4(unsigned& r0, unsigned& r1,
                                        unsigned& r2, unsigned& r3, uint32_t addr) {
    asm volatile("ldmatrix.sync.aligned.m8n8.x4.shared.b16 {%0,%1,%2,%3}, [%4];"
                 : "=r"(r0), "=r"(r1), "=r"(r2), "=r"(r3) : "r"(addr));
}
__device__ __forceinline__ void ldsm_x2(unsigned& r0, unsigned& r1, uint32_t addr) {
    asm volatile("ldmatrix.sync.aligned.m8n8.x2.shared.b16 {%0,%1}, [%2];"
                 : "=r"(r0), "=r"(r1) : "r"(addr));
}

// ---------------------------------------------------------------------------
// TF32 tensor-core GEMM, software-pipelined + double-buffered smem (R6 best).
// C[M,N] = A[M,K] * B[N,K]^T + bias[N]
// ---------------------------------------------------------------------------
template<int NN, int KK>
__global__ __launch_bounds__(256)
void gemm_tf32(const float* __restrict__ A, const float* __restrict__ B,
               const float* __restrict__ bias, float* __restrict__ C)
{
    __shared__ unsigned As[2][16][136];
    __shared__ unsigned Bs[2][16][136];

    const int bm   = blockIdx.y * 128;
    const int bn   = blockIdx.x * 128;
    const int tid  = threadIdx.x;
    const int warp = tid >> 5;
    const int lane = tid & 31;
    const int wm   = warp >> 2;
    const int wn   = warp & 3;
    const int r    = lane >> 2;
    const int c    = lane & 3;
    const int lrow = tid >> 2;
    const int lcol = (tid & 3) << 2;

    float acc[4][4][4];
    #pragma unroll
    for (int mt = 0; mt < 4; mt++)
        #pragma unroll
        for (int nt = 0; nt < 4; nt++)
            #pragma unroll
            for (int i = 0; i < 4; i++) acc[mt][nt][i] = 0.0f;

    const float* Aptr = A + (size_t)(bm + lrow) * KK + lcol;
    const float* Bptr = B + (size_t)(bn + lrow) * KK + lcol;

    float4 ga0, ga1, gb0, gb1;
    ga0 = *(const float4*)(Aptr);
    ga1 = *(const float4*)(Aptr + (size_t)64 * KK);
    gb0 = *(const float4*)(Bptr);
    gb1 = *(const float4*)(Bptr + (size_t)64 * KK);

    {
        float av0[4] = {ga0.x, ga0.y, ga0.z, ga0.w};
        float av1[4] = {ga1.x, ga1.y, ga1.z, ga1.w};
        float bv0[4] = {gb0.x, gb0.y, gb0.z, gb0.w};
        float bv1[4] = {gb1.x, gb1.y, gb1.z, gb1.w};
        #pragma unroll
        for (int j = 0; j < 4; j++) {
            int k = lcol + j;
            int s = ((k >> 2) & 3) << 3;
            As[0][k][lrow ^ s]        = f2tf32(av0[j]);
            As[0][k][(lrow + 64) ^ s] = f2tf32(av1[j]);
            Bs[0][k][lrow ^ s]        = f2tf32(bv0[j]);
            Bs[0][k][(lrow + 64) ^ s] = f2tf32(bv1[j]);
        }
    }
    __syncthreads();

    const int NKT = KK / 16;
    for (int kt = 0; kt < NKT; kt++) {
        const int cur = kt & 1;
        if (kt + 1 < NKT) {
            const int k0 = (kt + 1) * 16;
            ga0 = *(const float4*)(Aptr + k0);
            ga1 = *(const float4*)(Aptr + (size_t)64 * KK + k0);
            gb0 = *(const float4*)(Bptr + k0);
            gb1 = *(const float4*)(Bptr + (size_t)64 * KK + k0);
        }

        #pragma unroll
        for (int kc = 0; kc < 16; kc += 8) {
            const int s0 = ((kc >> 2) & 3) << 3;
            const int s1 = (((kc >> 2) + 1) & 3) << 3;

            unsigned af[4][4], bf[4][2];
            #pragma unroll
            for (int mt = 0; mt < 4; mt++) {
                const int mb = wm * 64 + mt * 16;
                af[mt][0] = As[cur][kc + c][(mb + r) ^ s0];
                af[mt][1] = As[cur][kc + c][(mb + r + 8) ^ s0];
                af[mt][2] = As[cur][kc + c + 4][(mb + r) ^ s1];
                af[mt][3] = As[cur][kc + c + 4][(mb + r + 8) ^ s1];
            }
            #pragma unroll
            for (int nt = 0; nt < 4; nt++) {
                const int nb = wn * 32 + nt * 8;
                bf[nt][0] = Bs[cur][kc + c][(nb + r) ^ s0];
                bf[nt][1] = Bs[cur][kc + c + 4][(nb + r) ^ s1];
            }
            #pragma unroll
            for (int mt = 0; mt < 4; mt++)
                #pragma unroll
                for (int nt = 0; nt < 4; nt++)
                    mma_tf32(acc[mt][nt], af[mt][0], af[mt][1], af[mt][2], af[mt][3],
                             bf[nt][0], bf[nt][1]);
        }

        if (kt + 1 < NKT) {
            const int nxt = cur ^ 1;
            float av0[4] = {ga0.x, ga0.y, ga0.z, ga0.w};
            float av1[4] = {ga1.x, ga1.y, ga1.z, ga1.w};
            float bv0[4] = {gb0.x, gb0.y, gb0.z, gb0.w};
            float bv1[4] = {gb1.x, gb1.y, gb1.z, gb1.w};
            #pragma unroll
            for (int j = 0; j < 4; j++) {
                int k = lcol + j;
                int s = ((k >> 2) & 3) << 3;
                As[nxt][k][lrow ^ s]        = f2tf32(av0[j]);
                As[nxt][k][(lrow + 64) ^ s] = f2tf32(av1[j]);
                Bs[nxt][k][lrow ^ s]        = f2tf32(bv0[j]);
                Bs[nxt][k][(lrow + 64) ^ s] = f2tf32(bv1[j]);
            }
            __syncthreads();
        }
    }

    #pragma unroll
    for (int nt = 0; nt < 4; nt++) {
        const int col = bn + wn * 32 + nt * 8 + 2 * c;
        const float2 bb = *(const float2*)(bias + col);
        #pragma unroll
        for (int mt = 0; mt < 4; mt++) {
            const int row0 = bm + wm * 64 + mt * 16 + r;
            float2 o0 = make_float2(acc[mt][nt][0] + bb.x, acc[mt][nt][1] + bb.y);
            float2 o1 = make_float2(acc[mt][nt][2] + bb.x, acc[mt][nt][3] + bb.y);
            *(float2*)&C[(size_t)row0 * NN + col]       = o0;
            *(float2*)&C[(size_t)(row0 + 8) * NN + col] = o1;
        }
    }
}

// ---------------------------------------------------------------------------
// RoPE in-place on q,k halves of g_qkv.
// ---------------------------------------------------------------------------
__global__ __launch_bounds__(256)
void rope_kernel(const float* __restrict__ cosT, const float* __restrict__ sinT)
{
    int idx = blockIdx.x * blockDim.x + threadIdx.x;
    const int total = SQ * 2 * NH * HALF;
    if (idx >= total) return;
    int d  = idx % HALF;
    int h  = (idx / HALF) % NH;
    int qk = (idx / (HALF * NH)) & 1;
    int s  = idx / (HALF * NH * 2);

    float* base = g_qkv + (size_t)s * QKV3 + qk * EMB + h * HD;
    float x1 = base[d];
    float x2 = base[d + HALF];
    float c  = cosT[(size_t)s * HD + d];
    float sn = sinT[(size_t)s * HD + d];
    base[d]        = x1 * c - x2 * sn;
    base[d + HALF] = x2 * c + x1 * sn;
}

// ---------------------------------------------------------------------------
// Tensor-core block-diagonal varlen flash attention, ldmatrix fragment loads.
// Q raw (split at load); K staged hi/lo; V stored transposed [dim][key];
// P stored [query][key]. S^T = K·Q^T 3xTF32; O^T = V^T·P^T single tf32.
// Smem ~96 KB => 2 CTAs/SM.
// ---------------------------------------------------------------------------
#define ATTN_SMEM_BYTES ((BQ*QSTR + 2*BK*KSTR + 80*VTSTR + BQ*PQSTR) * 4 + (64 + 64 + 16) * 4)

__global__ __launch_bounds__(256, 2)
void attn_kernel(const float* __restrict__ qkv, const int* __restrict__ cu,
                 float* __restrict__ out)
{
    extern __shared__ float sm[];
    float* Qs = sm;                       // [64][QSTR] raw Q (query, dim)
    float* Kh = Qs + BQ * QSTR;           // [64][KSTR] tf32-hi of K (key, dim)
    float* Kl = Kh + BK * KSTR;           // [64][KSTR] tf32-lo of K
    float* Vt = Kl + BK * KSTR;           // [80][VTSTR] tf32 V^T (dim, key), dims 72..79 zero
    float* Pq = Vt + 80 * VTSTR;          // [64][PQSTR] tf32 P (query, key)
    int* segq = (int*)(Pq + BQ * PQSTR);
    int* segk = segq + 64;
    int* cus  = segk + 64;

    const int tid  = threadIdx.x;
    const int lane = tid & 31;
    const int warp = tid >> 5;
    const int r    = lane >> 2;
    const int cq   = lane & 3;
    const int nb   = warp * 8;
    const int h    = blockIdx.y;
    const int q0   = blockIdx.x * BQ;

    // ldmatrix per-lane address components (byte offsets into shared space)
    const uint32_t uBase = (uint32_t)__cvta_generic_to_shared(sm);
    const uint32_t uQ  = uBase;
    const uint32_t uKh = uQ  + BQ * QSTR * 4;
    const uint32_t uKl = uKh + BK * KSTR * 4;
    const uint32_t uVt = uKl + BK * KSTR * 4;
    const uint32_t uPq = uVt + 80 * VTSTR * 4;

    const int lm16  = lane & 15;
    const int lsel4 = (lane >> 4) & 1;
    const int lm8   = lane & 7;
    const int lsel2 = (lane >> 3) & 1;
    const uint32_t aQ = uQ  + (uint32_t)((nb + lm8) * QSTR + lsel2 * 4) * 4;
    const uint32_t aK = (uint32_t)(lm16 * KSTR + lsel4 * 4) * 4;   // + uKh/uKl + (mt*16*KSTR + k0)*4
    const uint32_t aV = uVt + (uint32_t)(lm16 * VTSTR + lsel4 * 4) * 4;
    const uint32_t aP = uPq + (uint32_t)((nb + lm8) * PQSTR + lsel2 * 4) * 4;

    if (tid <= NSEG) cus[tid] = cu[tid];
    __syncthreads();

    if (tid < BQ) {
        int p = q0 + tid;
        int s = 0;
        #pragma unroll
        for (int i = 1; i <= NSEG; i++) s += (p >= cus[i]);
        segq[tid] = s;
    }
    // load Q tile raw
    #pragma unroll
    for (int it = 0; it < (BQ * HD) / 256; it++) {
        int idx = tid + it * 256;
        int d = idx % HD, row = idx / HD;
        Qs[row * QSTR + d] = qkv[(size_t)(q0 + row) * QKV3 + h * HD + d];
    }
    // zero Vt padding rows (dims 72..79) over all 64 key columns
    for (int i = tid; i < 8 * 64; i += 256)
        Vt[(HD + (i >> 6)) * VTSTR + (i & 63)] = 0.0f;
    __syncthreads();

    const int sq0 = segq[nb + 2 * cq];
    const int sq1 = segq[nb + 2 * cq + 1];
    const int k_lo = cus[segq[0]];
    const int k_hi = cus[segq[BQ - 1] + 1];

    float m[2]  = {-1e30f, -1e30f};
    float l[2]  = {0.0f, 0.0f};
    float oa[5][4];
    #pragma unroll
    for (int mt = 0; mt < 5; mt++)
        #pragma unroll
        for (int i = 0; i < 4; i++) oa[mt][i] = 0.0f;

    const float scale = 0.11785113019775793f;  // 1/sqrt(72)

    for (int kk0 = k_lo; kk0 < k_hi; kk0 += BK) {
        // ---- load K (split hi/lo) and V^T (tf32) tiles ----
        #pragma unroll
        for (int it = 0; it < (BK * HD) / 256; it++) {
            int idx = tid + it * 256;
            int d = idx % HD, ky = idx / HD;
            int key = kk0 + ky;
            float kv = 0.0f, vv = 0.0f;
            if (key < k_hi) {
                const float* row = qkv + (size_t)key * QKV3 + h * HD + d;
                kv = row[EMB];
                vv = row[2 * EMB];
            }
            unsigned hb = f2tf32(kv);
            float lo = kv - __uint_as_float(hb);
            Kh[ky * KSTR + d] = __uint_as_float(hb);
            Kl[ky * KSTR + d] = __uint_as_float(f2tf32(lo));
            Vt[d * VTSTR + ky] = __uint_as_float(f2tf32(vv));
        }
        if (tid < BK) {
            int key = kk0 + tid;
            int s = -1;
            if (key < k_hi) {
                s = 0;
                #pragma unroll
                for (int i = 1; i <= NSEG; i++) s += (key >= cus[i]);
            }
            segk[tid] = s;
        }
        __syncthreads();

        // ---- S^T = K·Q^T, 3xTF32: Kh*Qh + Kh*Ql + Kl*Qh ----
        float sf[4][4];
        #pragma unroll
        for (int mt = 0; mt < 4; mt++)
            #pragma unroll
            for (int i = 0; i < 4; i++) sf[mt][i] = 0.0f;

        #pragma unroll
        for (int k0 = 0; k0 < HD; k0 += 8) {
            unsigned qr0, qr1;
            ldsm_x2(qr0, qr1, aQ + k0 * 4);
            float q0v = __uint_as_float(qr0);
            float q1v = __uint_as_float(qr1);
            unsigned bh0 = f2tf32(q0v);
            unsigned bh1 = f2tf32(q1v);
            unsigned bl0 = f2tf32(q0v - __uint_as_float(bh0));
            unsigned bl1 = f2tf32(q1v - __uint_as_float(bh1));
            #pragma unroll
            for (int mt = 0; mt < 4; mt++) {
                const uint32_t koff = aK + (uint32_t)(mt * 16 * KSTR + k0) * 4;
                unsigned ah0, ah1, ah2, ah3, al0, al1, al2, al3;
                ldsm_x4(ah0, ah1, ah2, ah3, uKh + koff);
                ldsm_x4(al0, al1, al2, al3, uKl + koff);
                mma_tf32(sf[mt], ah0, ah1, ah2, ah3, bh0, bh1);
                mma_tf32(sf[mt], ah0, ah1, ah2, ah3, bl0, bl1);
                mma_tf32(sf[mt], al0, al1, al2, al3, bh0, bh1);
            }
        }

        int skr[4][2];
        #pragma unroll
        for (int mt = 0; mt < 4; mt++) {
            skr[mt][0] = segk[mt * 16 + r];
            skr[mt][1] = segk[mt * 16 + r + 8];
        }

        // ---- online softmax per query column ----
        const int sqv[2] = {sq0, sq1};
        #pragma unroll
        for (int qq = 0; qq < 2; qq++) {
            float mx = -1e30f;
            #pragma unroll
            for (int mt = 0; mt < 4; mt++) {
                float v0 = (skr[mt][0] == sqv[qq]) ? sf[mt][qq] * scale     : -1e30f;
                float v1 = (skr[mt][1] == sqv[qq]) ? sf[mt][qq + 2] * scale : -1e30f;
                sf[mt][qq]     = v0;
                sf[mt][qq + 2] = v1;
                mx = fmaxf(mx, fmaxf(v0, v1));
            }
            mx = fmaxf(mx, __shfl_xor_sync(0xffffffffu, mx, 4));
            mx = fmaxf(mx, __shfl_xor_sync(0xffffffffu, mx, 8));
            mx = fmaxf(mx, __shfl_xor_sync(0xffffffffu, mx, 16));

            float mn  = fmaxf(m[qq], mx);
            float fac = __expf(m[qq] - mn);
            m[qq] = mn;

            float sum = 0.0f;
            #pragma unroll
            for (int mt = 0; mt < 4; mt++) {
                float p0 = (sf[mt][qq]     > -1e29f) ? __expf(sf[mt][qq]     - mn) : 0.0f;
                float p1 = (sf[mt][qq + 2] > -1e29f) ? __expf(sf[mt][qq + 2] - mn) : 0.0f;
                sf[mt][qq]     = p0;
                sf[mt][qq + 2] = p1;
                sum += p0 + p1;
            }
            sum += __shfl_xor_sync(0xffffffffu, sum, 4);
            sum += __shfl_xor_sync(0xffffffffu, sum, 8);
            sum += __shfl_xor_sync(0xffffffffu, sum, 16);
            l[qq] = l[qq] * fac + sum;

            #pragma unroll
            for (int mt = 0; mt < 5; mt++) {
                oa[mt][qq]     *= fac;
                oa[mt][qq + 2] *= fac;
            }
        }

        // ---- stage P as [query][key] (rna tf32); bank = (8cq + r) distinct ----
        #pragma unroll
        for (int mt = 0; mt < 4; mt++) {
            #pragma unroll
            for (int half = 0; half < 2; half++) {
                const int krow = mt * 16 + r + half * 8;
                unsigned h0 = f2tf32(sf[mt][half * 2]);
                unsigned h1 = f2tf32(sf[mt][half * 2 + 1]);
                Pq[(nb + 2 * cq)     * PQSTR + krow] = __uint_as_float(h0);
                Pq[(nb + 2 * cq + 1) * PQSTR + krow] = __uint_as_float(h1);
            }
        }
        __syncthreads();

        // ---- O^T += V^T·P^T ----
        #pragma unroll
        for (int k0 = 0; k0 < BK; k0 += 8) {
            unsigned b0, b1;
            ldsm_x2(b0, b1, aP + k0 * 4);
            #pragma unroll
            for (int mt = 0; mt < 5; mt++) {
                unsigned a0, a1, a2, a3;
                ldsm_x4(a0, a1, a2, a3, aV + (uint32_t)(mt * 16 * VTSTR + k0) * 4);
                mma_tf32(oa[mt], a0, a1, a2, a3, b0, b1);
            }
        }
        __syncthreads();
    }

    // ---- normalize + store ----
    const float inv0 = 1.0f / l[0];
    const float inv1 = 1.0f / l[1];
    const size_t qa = (size_t)(q0 + nb + 2 * cq);
    const size_t qb = qa + 1;
    #pragma unroll
    for (int mt = 0; mt < 5; mt++) {
        int d0 = mt * 16 + r;
        int d1 = d0 + 8;
        if (d0 < HD) {
            out[qa * EMB + h * HD + d0] = oa[mt][0] * inv0;
            out[qb * EMB + h * HD + d0] = oa[mt][1] * inv1;
        }
        if (d1 < HD) {
            out[qa * EMB + h * HD + d1] = oa[mt][2] * inv0;
            out[qb * EMB + h * HD + d1] = oa[mt][3] * inv1;
        }
    }
}

// ---------------------------------------------------------------------------
extern "C" void kernel_launch(void* const* d_in, const int* in_sizes, int n_in,
                              void* d_out, int out_size)
{
    const float* hidden = (const float*)d_in[0];
    const int*   cu     = (const int*)  d_in[1];
    const float* cosT   = (const float*)d_in[2];
    const float* sinT   = (const float*)d_in[3];
    const float* w_qkv  = (const float*)d_in[4];
    const float* b_qkv  = (const float*)d_in[5];
    const float* w_out  = (const float*)d_in[6];
    const float* b_out  = (const float*)d_in[7];
    float* out = (float*)d_out;

    void* p_qkv = nullptr;
    void* p_attn = nullptr;
    cudaGetSymbolAddress(&p_qkv, g_qkv);
    cudaGetSymbolAddress(&p_attn, g_attn);
    float* qkv  = (float*)p_qkv;
    float* attn = (float*)p_attn;

    // 1) QKV projection
    dim3 g1(QKV3 / 128, SQ / 128);
    gemm_tf32<QKV3, EMB><<<g1, 256>>>(hidden, w_qkv, b_qkv, qkv);

    // 2) RoPE in place
    const int total = SQ * 2 * NH * HALF;
    rope_kernel<<<(total + 255) / 256, 256>>>(cosT, sinT);

    // 3) varlen block-diagonal attention (ldmatrix, 2 CTAs/SM)
    cudaFuncSetAttribute(attn_kernel, cudaFuncAttributeMaxDynamicSharedMemorySize,
                         ATTN_SMEM_BYTES);
    attn_kernel<<<dim3(SQ / BQ, NH), 256, ATTN_SMEM_BYTES>>>(qkv, cu, attn);

    // 4) output projection
    dim3 g2(EMB / 128, SQ / 128);
    gemm_tf32<EMB, EMB><<<g2, 256>>>(attn, w_out, b_out, out);
}

// round 14
// speedup vs baseline: 1.2714x; 1.1172x over previous
#include <cuda_runtime.h>
#include <cuda_bf16.h>
#include <stdint.h>
#include <math.h>

#define SQ   4096
#define EMB  1152
#define NH   16
#define HD   72
#define HALF 36
#define NSEG 8
#define QKV3 (3*EMB)

#define BQ 64
#define BK 64

#define KSB   88   // bf16 elems per row for Qh/Ql/Kh/Kl (176-byte rows)
#define VTSTR 68   // V^T f32 stride (keys + pad), 272B rows
#define PQSTR 68   // P[query][key] f32 stride, 272B rows

// byte layout of attention smem
#define OFF_QH  0
#define OFF_QL  (OFF_QH + BQ*KSB*2)
#define OFF_KH  (OFF_QL + BQ*KSB*2)
#define OFF_KL  (OFF_KH + BK*KSB*2)
#define OFF_VT  (OFF_KL + BK*KSB*2)
#define OFF_PQ  (OFF_VT + 80*VTSTR*4)
#define OFF_INT (OFF_PQ + BQ*PQSTR*4)
#define ATTN_SMEM_BYTES (OFF_INT + (64 + 64 + 16) * 4)

static __device__ float g_qkv[(size_t)SQ * QKV3];   // (S, 3E) scratch
static __device__ float g_attn[(size_t)SQ * EMB];   // (S, E) attention output

// ---------------------------------------------------------------------------
// helpers
// ---------------------------------------------------------------------------
__device__ __forceinline__ unsigned f2tf32(float x) {
    unsigned r;
    asm("cvt.rna.tf32.f32 %0, %1;" : "=r"(r) : "f"(x));
    return r;
}

__device__ __forceinline__ void mma_tf32(float c[4],
                                         unsigned a0, unsigned a1, unsigned a2, unsigned a3,
                                         unsigned b0, unsigned b1) {
    asm("mma.sync.aligned.m16n8k8.row.col.f32.tf32.tf32.f32 "
        "{%0,%1,%2,%3}, {%4,%5,%6,%7}, {%8,%9}, {%0,%1,%2,%3};"
        : "+f"(c[0]), "+f"(c[1]), "+f"(c[2]), "+f"(c[3])
        : "r"(a0), "r"(a1), "r"(a2), "r"(a3), "r"(b0), "r"(b1));
}

__device__ __forceinline__ void mma_bf16(float c[4],
                                         unsigned a0, unsigned a1, unsigned a2, unsigned a3,
                                         unsigned b0, unsigned b1) {
    asm("mma.sync.aligned.m16n8k16.row.col.f32.bf16.bf16.f32 "
        "{%0,%1,%2,%3}, {%4,%5,%6,%7}, {%8,%9}, {%0,%1,%2,%3};"
        : "+f"(c[0]), "+f"(c[1]), "+f"(c[2]), "+f"(c[3])
        : "r"(a0), "r"(a1), "r"(a2), "r"(a3), "r"(b0), "r"(b1));
}

__device__ __forceinline__ void ldsm_x4(unsigned& r0, unsigned& r1,
                                        unsigned& r2, unsigned& r3, uint32_t addr) {
    asm volatile("ldmatrix.sync.aligned.m8n8.x4.shared.b16 {%0,%1,%2,%3}, [%4];"
                 : "=r"(r0), "=r"(r1), "=r"(r2), "=r"(r3) : "r"(addr));
}
__device__ __forceinline__ void ldsm_x2(unsigned& r0, unsigned& r1, uint32_t addr) {
    asm volatile("ldmatrix.sync.aligned.m8n8.x2.shared.b16 {%0,%1}, [%2];"
                 : "=r"(r0), "=r"(r1) : "r"(addr));
}

// split float -> packed bf16x2 pair (lo halfword = first element)
__device__ __forceinline__ void bf16_split2(float x, float y, unsigned& hi, unsigned& lo) {
    __nv_bfloat16 hx = __float2bfloat16_rn(x);
    __nv_bfloat16 hy = __float2bfloat16_rn(y);
    __nv_bfloat16 lx = __float2bfloat16_rn(x - __bfloat162float(hx));
    __nv_bfloat16 ly = __float2bfloat16_rn(y - __bfloat162float(hy));
    hi = ((unsigned)__bfloat16_as_ushort(hy) << 16) | __bfloat16_as_ushort(hx);
    lo = ((unsigned)__bfloat16_as_ushort(ly) << 16) | __bfloat16_as_ushort(lx);
}

// ---------------------------------------------------------------------------
// TF32 tensor-core GEMM, software-pipelined + double-buffered smem (R6 best).
// ---------------------------------------------------------------------------
template<int NN, int KK>
__global__ __launch_bounds__(256)
void gemm_tf32(const float* __restrict__ A, const float* __restrict__ B,
               const float* __restrict__ bias, float* __restrict__ C)
{
    __shared__ unsigned As[2][16][136];
    __shared__ unsigned Bs[2][16][136];

    const int bm   = blockIdx.y * 128;
    const int bn   = blockIdx.x * 128;
    const int tid  = threadIdx.x;
    const int warp = tid >> 5;
    const int lane = tid & 31;
    const int wm   = warp >> 2;
    const int wn   = warp & 3;
    const int r    = lane >> 2;
    const int c    = lane & 3;
    const int lrow = tid >> 2;
    const int lcol = (tid & 3) << 2;

    float acc[4][4][4];
    #pragma unroll
    for (int mt = 0; mt < 4; mt++)
        #pragma unroll
        for (int nt = 0; nt < 4; nt++)
            #pragma unroll
            for (int i = 0; i < 4; i++) acc[mt][nt][i] = 0.0f;

    const float* Aptr = A + (size_t)(bm + lrow) * KK + lcol;
    const float* Bptr = B + (size_t)(bn + lrow) * KK + lcol;

    float4 ga0, ga1, gb0, gb1;
    ga0 = *(const float4*)(Aptr);
    ga1 = *(const float4*)(Aptr + (size_t)64 * KK);
    gb0 = *(const float4*)(Bptr);
    gb1 = *(const float4*)(Bptr + (size_t)64 * KK);

    {
        float av0[4] = {ga0.x, ga0.y, ga0.z, ga0.w};
        float av1[4] = {ga1.x, ga1.y, ga1.z, ga1.w};
        float bv0[4] = {gb0.x, gb0.y, gb0.z, gb0.w};
        float bv1[4] = {gb1.x, gb1.y, gb1.z, gb1.w};
        #pragma unroll
        for (int j = 0; j < 4; j++) {
            int k = lcol + j;
            int s = ((k >> 2) & 3) << 3;
            As[0][k][lrow ^ s]        = f2tf32(av0[j]);
            As[0][k][(lrow + 64) ^ s] = f2tf32(av1[j]);
            Bs[0][k][lrow ^ s]        = f2tf32(bv0[j]);
            Bs[0][k][(lrow + 64) ^ s] = f2tf32(bv1[j]);
        }
    }
    __syncthreads();

    const int NKT = KK / 16;
    for (int kt = 0; kt < NKT; kt++) {
        const int cur = kt & 1;
        if (kt + 1 < NKT) {
            const int k0 = (kt + 1) * 16;
            ga0 = *(const float4*)(Aptr + k0);
            ga1 = *(const float4*)(Aptr + (size_t)64 * KK + k0);
            gb0 = *(const float4*)(Bptr + k0);
            gb1 = *(const float4*)(Bptr + (size_t)64 * KK + k0);
        }

        #pragma unroll
        for (int kc = 0; kc < 16; kc += 8) {
            const int s0 = ((kc >> 2) & 3) << 3;
            const int s1 = (((kc >> 2) + 1) & 3) << 3;

            unsigned af[4][4], bf[4][2];
            #pragma unroll
            for (int mt = 0; mt < 4; mt++) {
                const int mb = wm * 64 + mt * 16;
                af[mt][0] = As[cur][kc + c][(mb + r) ^ s0];
                af[mt][1] = As[cur][kc + c][(mb + r + 8) ^ s0];
                af[mt][2] = As[cur][kc + c + 4][(mb + r) ^ s1];
                af[mt][3] = As[cur][kc + c + 4][(mb + r + 8) ^ s1];
            }
            #pragma unroll
            for (int nt = 0; nt < 4; nt++) {
                const int nb = wn * 32 + nt * 8;
                bf[nt][0] = Bs[cur][kc + c][(nb + r) ^ s0];
                bf[nt][1] = Bs[cur][kc + c + 4][(nb + r) ^ s1];
            }
            #pragma unroll
            for (int mt = 0; mt < 4; mt++)
                #pragma unroll
                for (int nt = 0; nt < 4; nt++)
                    mma_tf32(acc[mt][nt], af[mt][0], af[mt][1], af[mt][2], af[mt][3],
                             bf[nt][0], bf[nt][1]);
        }

        if (kt + 1 < NKT) {
            const int nxt = cur ^ 1;
            float av0[4] = {ga0.x, ga0.y, ga0.z, ga0.w};
            float av1[4] = {ga1.x, ga1.y, ga1.z, ga1.w};
            float bv0[4] = {gb0.x, gb0.y, gb0.z, gb0.w};
            float bv1[4] = {gb1.x, gb1.y, gb1.z, gb1.w};
            #pragma unroll
            for (int j = 0; j < 4; j++) {
                int k = lcol + j;
                int s = ((k >> 2) & 3) << 3;
                As[nxt][k][lrow ^ s]        = f2tf32(av0[j]);
                As[nxt][k][(lrow + 64) ^ s] = f2tf32(av1[j]);
                Bs[nxt][k][lrow ^ s]        = f2tf32(bv0[j]);
                Bs[nxt][k][(lrow + 64) ^ s] = f2tf32(bv1[j]);
            }
            __syncthreads();
        }
    }

    #pragma unroll
    for (int nt = 0; nt < 4; nt++) {
        const int col = bn + wn * 32 + nt * 8 + 2 * c;
        const float2 bb = *(const float2*)(bias + col);
        #pragma unroll
        for (int mt = 0; mt < 4; mt++) {
            const int row0 = bm + wm * 64 + mt * 16 + r;
            float2 o0 = make_float2(acc[mt][nt][0] + bb.x, acc[mt][nt][1] + bb.y);
            float2 o1 = make_float2(acc[mt][nt][2] + bb.x, acc[mt][nt][3] + bb.y);
            *(float2*)&C[(size_t)row0 * NN + col]       = o0;
            *(float2*)&C[(size_t)(row0 + 8) * NN + col] = o1;
        }
    }
}

// ---------------------------------------------------------------------------
// RoPE in-place on q,k halves of g_qkv.
// ---------------------------------------------------------------------------
__global__ __launch_bounds__(256)
void rope_kernel(const float* __restrict__ cosT, const float* __restrict__ sinT)
{
    int idx = blockIdx.x * blockDim.x + threadIdx.x;
    const int total = SQ * 2 * NH * HALF;
    if (idx >= total) return;
    int d  = idx % HALF;
    int h  = (idx / HALF) % NH;
    int qk = (idx / (HALF * NH)) & 1;
    int s  = idx / (HALF * NH * 2);

    float* base = g_qkv + (size_t)s * QKV3 + qk * EMB + h * HD;
    float x1 = base[d];
    float x2 = base[d + HALF];
    float c  = cosT[(size_t)s * HD + d];
    float sn = sinT[(size_t)s * HD + d];
    base[d]        = x1 * c - x2 * sn;
    base[d + HALF] = x2 * c + x1 * sn;
}

// ---------------------------------------------------------------------------
// Tensor-core block-diagonal varlen flash attention.
// S^T = K·Q^T via 3xBF16 split (m16n8k16): Kh*Qh + Kh*Ql + Kl*Qh.
// O^T = V^T·P^T single tf32 (m16n8k8). ldmatrix everywhere. ~85 KB smem.
// ---------------------------------------------------------------------------
__global__ __launch_bounds__(256, 2)
void attn_kernel(const float* __restrict__ qkv, const int* __restrict__ cu,
                 float* __restrict__ out)
{
    extern __shared__ char smb[];
    unsigned* QhW = (unsigned*)(smb + OFF_QH);   // packed bf16x2, row stride KSB/2 words
    unsigned* QlW = (unsigned*)(smb + OFF_QL);
    unsigned* KhW = (unsigned*)(smb + OFF_KH);
    unsigned* KlW = (unsigned*)(smb + OFF_KL);
    float*    Vt  = (float*)(smb + OFF_VT);      // [80][VTSTR] f32 (tf32 vals)
    float*    Pq  = (float*)(smb + OFF_PQ);      // [64][PQSTR] f32 (tf32 vals)
    int* segq = (int*)(smb + OFF_INT);
    int* segk = segq + 64;
    int* cus  = segk + 64;

    const int tid  = threadIdx.x;
    const int lane = tid & 31;
    const int warp = tid >> 5;
    const int r    = lane >> 2;
    const int cq   = lane & 3;
    const int nb   = warp * 8;
    const int h    = blockIdx.y;
    const int q0   = blockIdx.x * BQ;

    const uint32_t uBase = (uint32_t)__cvta_generic_to_shared(smb);
    const uint32_t uQh = uBase + OFF_QH;
    const uint32_t uQl = uBase + OFF_QL;
    const uint32_t uKh = uBase + OFF_KH;
    const uint32_t uKl = uBase + OFF_KL;
    const uint32_t uVt = uBase + OFF_VT;
    const uint32_t uPq = uBase + OFF_PQ;

    const int lm16  = lane & 15;
    const int lsel4 = (lane >> 4) & 1;
    const int lm8   = lane & 7;
    const int lsel2 = (lane >> 3) & 1;
    // bf16 ldmatrix lane addresses (176B rows)
    const uint32_t aQb = (uint32_t)((nb + lm8) * KSB * 2 + lsel2 * 16);  // + uQh/uQl + c5*32
    const uint32_t aKb = (uint32_t)(lm16 * KSB * 2 + lsel4 * 16);        // + uKh/uKl + mt*16*176 + c5*32
    // f32 ldmatrix lane addresses (PV phase, as R13)
    const uint32_t aV = uVt + (uint32_t)(lm16 * VTSTR + lsel4 * 4) * 4;
    const uint32_t aP = uPq + (uint32_t)((nb + lm8) * PQSTR + lsel2 * 4) * 4;

    if (tid <= NSEG) cus[tid] = cu[tid];
    __syncthreads();

    if (tid < BQ) {
        int p = q0 + tid;
        int s = 0;
        #pragma unroll
        for (int i = 1; i <= NSEG; i++) s += (p >= cus[i]);
        segq[tid] = s;
    }
    // stage Q hi/lo bf16 (once): 64 rows x 36 pairs
    #pragma unroll
    for (int it = 0; it < 9; it++) {
        int idx = tid + it * 256;
        int row = idx / 36, dp = (idx % 36) * 2;
        float2 q2 = *(const float2*)(qkv + (size_t)(q0 + row) * QKV3 + h * HD + dp);
        unsigned hi, lo;
        bf16_split2(q2.x, q2.y, hi, lo);
        QhW[(row * KSB + dp) >> 1] = hi;
        QlW[(row * KSB + dp) >> 1] = lo;
    }
    // zero bf16 pads dims 72..87 for Qh/Ql/Kh/Kl (8 words per row each)
    for (int i = tid; i < 64 * 8; i += 256) {
        int row = i >> 3, w = i & 7;
        int wi = (row * KSB + 72) / 2 + w;
        QhW[wi] = 0; QlW[wi] = 0; KhW[wi] = 0; KlW[wi] = 0;
    }
    // zero Vt pad rows 72..79
    for (int i = tid; i < 8 * 64; i += 256)
        Vt[(HD + (i >> 6)) * VTSTR + (i & 63)] = 0.0f;
    __syncthreads();

    const int sq0 = segq[nb + 2 * cq];
    const int sq1 = segq[nb + 2 * cq + 1];
    const int k_lo = cus[segq[0]];
    const int k_hi = cus[segq[BQ - 1] + 1];

    float m[2]  = {-1e30f, -1e30f};
    float l[2]  = {0.0f, 0.0f};
    float oa[5][4];
    #pragma unroll
    for (int mt = 0; mt < 5; mt++)
        #pragma unroll
        for (int i = 0; i < 4; i++) oa[mt][i] = 0.0f;

    const float scale = 0.11785113019775793f;  // 1/sqrt(72)

    for (int kk0 = k_lo; kk0 < k_hi; kk0 += BK) {
        // ---- stage K (bf16 hi/lo) and V^T (tf32 f32) ----
        #pragma unroll
        for (int it = 0; it < 9; it++) {
            int idx = tid + it * 256;
            int ky = idx / 36, dp = (idx % 36) * 2;
            int key = kk0 + ky;
            float2 k2 = make_float2(0.0f, 0.0f), v2 = make_float2(0.0f, 0.0f);
            if (key < k_hi) {
                const float* rowp = qkv + (size_t)key * QKV3 + h * HD + dp;
                k2 = *(const float2*)(rowp + EMB);
                v2 = *(const float2*)(rowp + 2 * EMB);
            }
            unsigned hi, lo;
            bf16_split2(k2.x, k2.y, hi, lo);
            KhW[(ky * KSB + dp) >> 1] = hi;
            KlW[(ky * KSB + dp) >> 1] = lo;
            Vt[dp * VTSTR + ky]       = __uint_as_float(f2tf32(v2.x));
            Vt[(dp + 1) * VTSTR + ky] = __uint_as_float(f2tf32(v2.y));
        }
        if (tid < BK) {
            int key = kk0 + tid;
            int s = -1;
            if (key < k_hi) {
                s = 0;
                #pragma unroll
                for (int i = 1; i <= NSEG; i++) s += (key >= cus[i]);
            }
            segk[tid] = s;
        }
        __syncthreads();

        // ---- S^T = K·Q^T, 3xBF16 (k16): Kh*Qh + Kh*Ql + Kl*Qh ----
        float sf[4][4];
        #pragma unroll
        for (int mt = 0; mt < 4; mt++)
            #pragma unroll
            for (int i = 0; i < 4; i++) sf[mt][i] = 0.0f;

        #pragma unroll
        for (int c5 = 0; c5 < 5; c5++) {
            unsigned bh0, bh1, bl0, bl1;
            ldsm_x2(bh0, bh1, uQh + aQb + c5 * 32);
            ldsm_x2(bl0, bl1, uQl + aQb + c5 * 32);
            #pragma unroll
            for (int mt = 0; mt < 4; mt++) {
                const uint32_t koff = aKb + (uint32_t)(mt * 16 * KSB * 2 + c5 * 32);
                unsigned ah0, ah1, ah2, ah3, al0, al1, al2, al3;
                ldsm_x4(ah0, ah1, ah2, ah3, uKh + koff);
                ldsm_x4(al0, al1, al2, al3, uKl + koff);
                mma_bf16(sf[mt], ah0, ah1, ah2, ah3, bh0, bh1);
                mma_bf16(sf[mt], ah0, ah1, ah2, ah3, bl0, bl1);
                mma_bf16(sf[mt], al0, al1, al2, al3, bh0, bh1);
            }
        }

        int skr[4][2];
        #pragma unroll
        for (int mt = 0; mt < 4; mt++) {
            skr[mt][0] = segk[mt * 16 + r];
            skr[mt][1] = segk[mt * 16 + r + 8];
        }

        // ---- online softmax per query column ----
        const int sqv[2] = {sq0, sq1};
        #pragma unroll
        for (int qq = 0; qq < 2; qq++) {
            float mx = -1e30f;
            #pragma unroll
            for (int mt = 0; mt < 4; mt++) {
                float v0 = (skr[mt][0] == sqv[qq]) ? sf[mt][qq] * scale     : -1e30f;
                float v1 = (skr[mt][1] == sqv[qq]) ? sf[mt][qq + 2] * scale : -1e30f;
                sf[mt][qq]     = v0;
                sf[mt][qq + 2] = v1;
                mx = fmaxf(mx, fmaxf(v0, v1));
            }
            mx = fmaxf(mx, __shfl_xor_sync(0xffffffffu, mx, 4));
            mx = fmaxf(mx, __shfl_xor_sync(0xffffffffu, mx, 8));
            mx = fmaxf(mx, __shfl_xor_sync(0xffffffffu, mx, 16));

            float mn  = fmaxf(m[qq], mx);
            float fac = __expf(m[qq] - mn);
            m[qq] = mn;

            float sum = 0.0f;
            #pragma unroll
            for (int mt = 0; mt < 4; mt++) {
                float p0 = (sf[mt][qq]     > -1e29f) ? __expf(sf[mt][qq]     - mn) : 0.0f;
                float p1 = (sf[mt][qq + 2] > -1e29f) ? __expf(sf[mt][qq + 2] - mn) : 0.0f;
                sf[mt][qq]     = p0;
                sf[mt][qq + 2] = p1;
                sum += p0 + p1;
            }
            sum += __shfl_xor_sync(0xffffffffu, sum, 4);
            sum += __shfl_xor_sync(0xffffffffu, sum, 8);
            sum += __shfl_xor_sync(0xffffffffu, sum, 16);
            l[qq] = l[qq] * fac + sum;

            #pragma unroll
            for (int mt = 0; mt < 5; mt++) {
                oa[mt][qq]     *= fac;
                oa[mt][qq + 2] *= fac;
            }
        }

        // ---- stage P as [query][key] (rna tf32) ----
        #pragma unroll
        for (int mt = 0; mt < 4; mt++) {
            #pragma unroll
            for (int half = 0; half < 2; half++) {
                const int krow = mt * 16 + r + half * 8;
                unsigned h0 = f2tf32(sf[mt][half * 2]);
                unsigned h1 = f2tf32(sf[mt][half * 2 + 1]);
                Pq[(nb + 2 * cq)     * PQSTR + krow] = __uint_as_float(h0);
                Pq[(nb + 2 * cq + 1) * PQSTR + krow] = __uint_as_float(h1);
            }
        }
        __syncthreads();

        // ---- O^T += V^T·P^T (tf32) ----
        #pragma unroll
        for (int k0 = 0; k0 < BK; k0 += 8) {
            unsigned b0, b1;
            ldsm_x2(b0, b1, aP + k0 * 4);
            #pragma unroll
            for (int mt = 0; mt < 5; mt++) {
                unsigned a0, a1, a2, a3;
                ldsm_x4(a0, a1, a2, a3, aV + (uint32_t)(mt * 16 * VTSTR + k0) * 4);
                mma_tf32(oa[mt], a0, a1, a2, a3, b0, b1);
            }
        }
        __syncthreads();
    }

    // ---- normalize + store ----
    const float inv0 = 1.0f / l[0];
    const float inv1 = 1.0f / l[1];
    const size_t qa = (size_t)(q0 + nb + 2 * cq);
    const size_t qb = qa + 1;
    #pragma unroll
    for (int mt = 0; mt < 5; mt++) {
        int d0 = mt * 16 + r;
        int d1 = d0 + 8;
        if (d0 < HD) {
            out[qa * EMB + h * HD + d0] = oa[mt][0] * inv0;
            out[qb * EMB + h * HD + d0] = oa[mt][1] * inv1;
        }
        if (d1 < HD) {
            out[qa * EMB + h * HD + d1] = oa[mt][2] * inv0;
            out[qb * EMB + h * HD + d1] = oa[mt][3] * inv1;
        }
    }
}

// ---------------------------------------------------------------------------
extern "C" void kernel_launch(void* const* d_in, const int* in_sizes, int n_in,
                              void* d_out, int out_size)
{
    const float* hidden = (const float*)d_in[0];
    const int*   cu     = (const int*)  d_in[1];
    const float* cosT   = (const float*)d_in[2];
    const float* sinT   = (const float*)d_in[3];
    const float* w_qkv  = (const float*)d_in[4];
    const float* b_qkv  = (const float*)d_in[5];
    const float* w_out  = (const float*)d_in[6];
    const float* b_out  = (const float*)d_in[7];
    float* out = (float*)d_out;

    void* p_qkv = nullptr;
    void* p_attn = nullptr;
    cudaGetSymbolAddress(&p_qkv, g_qkv);
    cudaGetSymbolAddress(&p_attn, g_attn);
    float* qkv  = (float*)p_qkv;
    float* attn = (float*)p_attn;

    // 1) QKV projection
    dim3 g1(QKV3 / 128, SQ / 128);
    gemm_tf32<QKV3, EMB><<<g1, 256>>>(hidden, w_qkv, b_qkv, qkv);

    // 2) RoPE in place
    const int total = SQ * 2 * NH * HALF;
    rope_kernel<<<(total + 255) / 256, 256>>>(cosT, sinT);

    // 3) varlen block-diagonal attention (3xBF16 S, tf32 PV, 2 CTAs/SM)
    cudaFuncSetAttribute(attn_kernel, cudaFuncAttributeMaxDynamicSharedMemorySize,
                         ATTN_SMEM_BYTES);
    attn_kernel<<<dim3(SQ / BQ, NH), 256, ATTN_SMEM_BYTES>>>(qkv, cu, attn);

    // 4) output projection
    dim3 g2(EMB / 128, SQ / 128);
    gemm_tf32<EMB, EMB><<<g2, 256>>>(attn, w_out, b_out, out);
}